// round 1
// baseline (speedup 1.0000x reference)
#include <cuda_runtime.h>
#include <math.h>

// Problem constants
#define B_   2
#define S_   2048
#define D_   1024
#define H_   16
#define DK_  64
#define M_   (B_*S_)     // 4096 rows (b*S+s)
#define NQKV (3*D_)      // 3072

// Scratch (device globals — no allocation allowed)
__device__ float g_Q[B_*H_*S_*DK_];
__device__ float g_K[B_*H_*S_*DK_];
__device__ float g_V[B_*H_*S_*DK_];
__device__ float g_attn[(size_t)M_*D_];

// ============================================================
// GEMM1: qkv = x @ W_qkv^T, fused RoPE epilogue, scatter to Q/K/V
//   C[m, e] = sum_d X[m,d] * Wqkv[e,d]
// 128x128 block tile, BK=8, 256 threads, 8x8 per-thread tile.
// ============================================================
#define G1_BM 128
#define G1_BN 128
#define G1_BK 8

__global__ __launch_bounds__(256)
void qkv_rope_kernel(const float* __restrict__ X,
                     const float* __restrict__ Wqkv,
                     const int*   __restrict__ pos)
{
    __shared__ float As[G1_BK][G1_BM];
    __shared__ float Bs[G1_BK][G1_BN];

    const int m0  = blockIdx.y * G1_BM;
    const int n0  = blockIdx.x * G1_BN;
    const int tid = threadIdx.x;
    const int ty  = tid >> 4;     // 0..15 -> rows ty*8..
    const int tx  = tid & 15;     // 0..15 -> cols tx*8..

    float acc[8][8];
    #pragma unroll
    for (int i = 0; i < 8; i++)
        #pragma unroll
        for (int j = 0; j < 8; j++) acc[i][j] = 0.f;

    const int lr = tid >> 1;          // 0..127
    const int lc = (tid & 1) * 4;     // 0 or 4

    for (int k0 = 0; k0 < D_; k0 += G1_BK) {
        float4 av = *(const float4*)(X    + (size_t)(m0 + lr) * D_ + k0 + lc);
        As[lc+0][lr] = av.x; As[lc+1][lr] = av.y;
        As[lc+2][lr] = av.z; As[lc+3][lr] = av.w;
        float4 bv = *(const float4*)(Wqkv + (size_t)(n0 + lr) * D_ + k0 + lc);
        Bs[lc+0][lr] = bv.x; Bs[lc+1][lr] = bv.y;
        Bs[lc+2][lr] = bv.z; Bs[lc+3][lr] = bv.w;
        __syncthreads();

        #pragma unroll
        for (int kk = 0; kk < G1_BK; kk++) {
            float4 a0 = *(const float4*)&As[kk][ty*8];
            float4 a1 = *(const float4*)&As[kk][ty*8+4];
            float4 b0 = *(const float4*)&Bs[kk][tx*8];
            float4 b1 = *(const float4*)&Bs[kk][tx*8+4];
            float af[8] = {a0.x,a0.y,a0.z,a0.w,a1.x,a1.y,a1.z,a1.w};
            float bf[8] = {b0.x,b0.y,b0.z,b0.w,b1.x,b1.y,b1.z,b1.w};
            #pragma unroll
            for (int i = 0; i < 8; i++)
                #pragma unroll
                for (int j = 0; j < 8; j++)
                    acc[i][j] = fmaf(af[i], bf[j], acc[i][j]);
        }
        __syncthreads();
    }

    // ---- Epilogue: RoPE for Q/K, plain scatter for V ----
    // Each thread's 8 columns are contiguous and never cross a 'which' (1024)
    // or head (64) boundary (base is a multiple of 8; 1024/64 multiples of 8).
    const int baseN = n0 + tx*8;
    const int which = baseN >> 10;          // 0:Q 1:K 2:V
    const int h     = (baseN & 1023) >> 6;
    const int dd0   = baseN & 63;

    if (which == 2) {
        #pragma unroll
        for (int i = 0; i < 8; i++) {
            int m = m0 + ty*8 + i;
            int bb = m >> 11, s = m & (S_-1);
            float* dst = g_V + ((size_t)((bb*H_ + h)*S_ + s))*DK_ + dd0;
            #pragma unroll
            for (int j = 0; j < 8; j++) dst[j] = acc[i][j];
        }
    } else {
        float* gdst = (which == 0) ? g_Q : g_K;
        // freq_p = theta^(-p/32), p = pair index
        float freqs[4];
        #pragma unroll
        for (int jp = 0; jp < 4; jp++) {
            int p = (dd0 + jp*2) >> 1;
            // exp2f(-p * log2(10000)/32)
            freqs[jp] = exp2f(-(float)p * (13.287712379549449f / 32.0f));
        }
        #pragma unroll
        for (int i = 0; i < 8; i++) {
            int m = m0 + ty*8 + i;
            int bb = m >> 11, s = m & (S_-1);
            float pf = (float)pos[m];
            float* dst = gdst + ((size_t)((bb*H_ + h)*S_ + s))*DK_ + dd0;
            #pragma unroll
            for (int jp = 0; jp < 4; jp++) {
                float ang = pf * freqs[jp];
                float sn, cs;
                sincosf(ang, &sn, &cs);
                float ve = acc[i][jp*2], vo = acc[i][jp*2+1];
                dst[jp*2]   = cs*ve - sn*vo;
                dst[jp*2+1] = sn*ve + cs*vo;
            }
        }
    }
}

// ============================================================
// Flash-attention (fp32, causal, online softmax)
// Block: 64 query rows x one (b,h). Key tiles of 32. 256 threads.
// ============================================================
#define A_BM 64
#define A_BN 32

__global__ __launch_bounds__(256)
void attn_kernel()
{
    __shared__ float Qt[DK_][A_BM + 1];   // [kk][row]
    __shared__ float Kt[DK_][A_BN + 1];   // [kk][key]
    __shared__ float Vs[A_BN][DK_ + 1];   // [key][dim]
    __shared__ float Ss[A_BM][A_BN + 4];  // scores / probs
    __shared__ float red[4][A_BM];
    __shared__ float row_m[A_BM], row_l[A_BM], row_a[A_BM];

    const int bh = blockIdx.y;
    const int m0 = blockIdx.x * A_BM;
    const float* Qp = g_Q + (size_t)bh * S_ * DK_;
    const float* Kp = g_K + (size_t)bh * S_ * DK_;
    const float* Vp = g_V + (size_t)bh * S_ * DK_;

    const int tid = threadIdx.x;
    const int ty  = tid >> 4;   // 0..15
    const int tx  = tid & 15;   // 0..15

    // Load Q tile transposed (coalesced gmem, conflict-free smem)
    for (int idx = tid; idx < A_BM * DK_; idx += 256) {
        int r = idx >> 6, d = idx & 63;
        Qt[d][r] = Qp[(size_t)(m0 + r) * DK_ + d];
    }
    if (tid < A_BM) { row_m[tid] = -1e30f; row_l[tid] = 0.f; }

    float o[4][4];
    #pragma unroll
    for (int i = 0; i < 4; i++)
        #pragma unroll
        for (int c = 0; c < 4; c++) o[i][c] = 0.f;

    const int nTiles = (m0 + A_BM) / A_BN;   // causal bound
    for (int t = 0; t < nTiles; t++) {
        const int n0 = t * A_BN;
        __syncthreads();  // protect Kt/Vs/Ss from previous iteration

        for (int idx = tid; idx < A_BN * DK_; idx += 256) {
            int j = idx >> 6, d = idx & 63;
            float kv = Kp[(size_t)(n0 + j) * DK_ + d];
            Kt[d][j] = kv;
            Vs[j][d] = Vp[(size_t)(n0 + j) * DK_ + d];
        }
        __syncthreads();

        // scores: rows ty*4+i, cols tx*2+c
        float s[4][2] = {{0.f,0.f},{0.f,0.f},{0.f,0.f},{0.f,0.f}};
        #pragma unroll 8
        for (int kk = 0; kk < DK_; kk++) {
            float aq[4], bk[2];
            #pragma unroll
            for (int i = 0; i < 4; i++) aq[i] = Qt[kk][ty*4 + i];
            #pragma unroll
            for (int c = 0; c < 2; c++) bk[c] = Kt[kk][tx*2 + c];
            #pragma unroll
            for (int i = 0; i < 4; i++)
                #pragma unroll
                for (int c = 0; c < 2; c++)
                    s[i][c] = fmaf(aq[i], bk[c], s[i][c]);
        }
        #pragma unroll
        for (int i = 0; i < 4; i++) {
            int qi = m0 + ty*4 + i;
            #pragma unroll
            for (int c = 0; c < 2; c++) {
                int kj = n0 + tx*2 + c;
                Ss[ty*4 + i][tx*2 + c] = (kj <= qi) ? s[i][c] * 0.125f : -1e30f;
            }
        }
        __syncthreads();

        // pass 1: tile row max
        {
            int r = tid & 63, q = tid >> 6;
            float mx = -1e30f;
            #pragma unroll
            for (int c8 = 0; c8 < 8; c8++) mx = fmaxf(mx, Ss[r][q*8 + c8]);
            red[q][r] = mx;
        }
        __syncthreads();
        if (tid < A_BM) {
            float mt = fmaxf(fmaxf(red[0][tid], red[1][tid]),
                             fmaxf(red[2][tid], red[3][tid]));
            float mo = row_m[tid];
            float mn = fmaxf(mo, mt);
            row_a[tid] = __expf(mo - mn);
            row_m[tid] = mn;
        }
        __syncthreads();

        // pass 2: exponentiate + partial sums
        {
            int r = tid & 63, q = tid >> 6;
            float mn = row_m[r];
            float ps = 0.f;
            #pragma unroll
            for (int c8 = 0; c8 < 8; c8++) {
                float p = __expf(Ss[r][q*8 + c8] - mn);
                Ss[r][q*8 + c8] = p;
                ps += p;
            }
            red[q][r] = ps;
        }
        __syncthreads();
        if (tid < A_BM) {
            row_l[tid] = row_l[tid] * row_a[tid]
                       + (red[0][tid] + red[1][tid] + red[2][tid] + red[3][tid]);
        }

        // rescale O, then accumulate P @ V  (rows ty*4+i, dims tx*4+c)
        float al[4];
        #pragma unroll
        for (int i = 0; i < 4; i++) al[i] = row_a[ty*4 + i];
        #pragma unroll
        for (int i = 0; i < 4; i++)
            #pragma unroll
            for (int c = 0; c < 4; c++) o[i][c] *= al[i];

        #pragma unroll 8
        for (int j = 0; j < A_BN; j++) {
            float pv[4], vv[4];
            #pragma unroll
            for (int i = 0; i < 4; i++) pv[i] = Ss[ty*4 + i][j];
            #pragma unroll
            for (int c = 0; c < 4; c++) vv[c] = Vs[j][tx*4 + c];
            #pragma unroll
            for (int i = 0; i < 4; i++)
                #pragma unroll
                for (int c = 0; c < 4; c++)
                    o[i][c] = fmaf(pv[i], vv[c], o[i][c]);
        }
    }
    __syncthreads();

    // write normalized output in [b*S+s][h*64+dd] layout
    const int bb = bh >> 4, h = bh & 15;
    #pragma unroll
    for (int i = 0; i < 4; i++) {
        int sidx = m0 + ty*4 + i;
        float inv = 1.0f / row_l[ty*4 + i];
        float* dst = g_attn + (size_t)(bb*S_ + sidx) * D_ + h*DK_ + tx*4;
        #pragma unroll
        for (int c = 0; c < 4; c++) dst[c] = o[i][c] * inv;
    }
}

// ============================================================
// GEMM2: out = attn @ W_o^T   (C[m,e] = sum_d A[m,d]*Wo[e,d])
// ============================================================
__global__ __launch_bounds__(256)
void out_gemm_kernel(const float* __restrict__ Wo,
                     float* __restrict__ out)
{
    __shared__ float As[G1_BK][G1_BM];
    __shared__ float Bs[G1_BK][G1_BN];

    const int m0  = blockIdx.y * G1_BM;
    const int n0  = blockIdx.x * G1_BN;
    const int tid = threadIdx.x;
    const int ty  = tid >> 4;
    const int tx  = tid & 15;

    float acc[8][8];
    #pragma unroll
    for (int i = 0; i < 8; i++)
        #pragma unroll
        for (int j = 0; j < 8; j++) acc[i][j] = 0.f;

    const int lr = tid >> 1;
    const int lc = (tid & 1) * 4;

    for (int k0 = 0; k0 < D_; k0 += G1_BK) {
        float4 av = *(const float4*)(g_attn + (size_t)(m0 + lr) * D_ + k0 + lc);
        As[lc+0][lr] = av.x; As[lc+1][lr] = av.y;
        As[lc+2][lr] = av.z; As[lc+3][lr] = av.w;
        float4 bv = *(const float4*)(Wo + (size_t)(n0 + lr) * D_ + k0 + lc);
        Bs[lc+0][lr] = bv.x; Bs[lc+1][lr] = bv.y;
        Bs[lc+2][lr] = bv.z; Bs[lc+3][lr] = bv.w;
        __syncthreads();

        #pragma unroll
        for (int kk = 0; kk < G1_BK; kk++) {
            float4 a0 = *(const float4*)&As[kk][ty*8];
            float4 a1 = *(const float4*)&As[kk][ty*8+4];
            float4 b0 = *(const float4*)&Bs[kk][tx*8];
            float4 b1 = *(const float4*)&Bs[kk][tx*8+4];
            float af[8] = {a0.x,a0.y,a0.z,a0.w,a1.x,a1.y,a1.z,a1.w};
            float bf[8] = {b0.x,b0.y,b0.z,b0.w,b1.x,b1.y,b1.z,b1.w};
            #pragma unroll
            for (int i = 0; i < 8; i++)
                #pragma unroll
                for (int j = 0; j < 8; j++)
                    acc[i][j] = fmaf(af[i], bf[j], acc[i][j]);
        }
        __syncthreads();
    }

    #pragma unroll
    for (int i = 0; i < 8; i++) {
        float* dst = out + (size_t)(m0 + ty*8 + i) * D_ + n0 + tx*8;
        #pragma unroll
        for (int j = 0; j < 8; j++) dst[j] = acc[i][j];
    }
}

// ============================================================
// Launch
// ============================================================
extern "C" void kernel_launch(void* const* d_in, const int* in_sizes, int n_in,
                              void* d_out, int out_size)
{
    const float* x    = (const float*)d_in[0];
    const int*   pos  = (const int*)  d_in[1];
    const float* wqkv = (const float*)d_in[2];
    const float* wo   = (const float*)d_in[3];
    float* out = (float*)d_out;

    (void)in_sizes; (void)n_in; (void)out_size;

    qkv_rope_kernel<<<dim3(NQKV / G1_BN, M_ / G1_BM), 256>>>(x, wqkv, pos);
    attn_kernel<<<dim3(S_ / A_BM, B_ * H_), 256>>>();
    out_gemm_kernel<<<dim3(D_ / G1_BN, M_ / G1_BM), 256>>>(wo, out);
}

// round 2
// speedup vs baseline: 3.1605x; 3.1605x over previous
#include <cuda_runtime.h>
#include <math.h>

// Problem constants
#define B_   2
#define S_   2048
#define D_   1024
#define H_   16
#define DK_  64
#define M_   (B_*S_)     // 4096
#define NQKV (3*D_)      // 3072

// Scratch (device globals — no allocation allowed)
__device__ float  g_Q[B_*H_*S_*DK_];
__device__ float  g_K[B_*H_*S_*DK_];
__device__ float  g_V[B_*H_*S_*DK_];
__device__ float  g_attn[(size_t)M_*D_];
__device__ float2 g_rope[2048*32];           // [pos][pair] = (cos, sin)

// ---------------- helpers ----------------
__device__ __forceinline__ unsigned f2tf(float x) {
    unsigned u;
    asm("cvt.rna.tf32.f32 %0, %1;" : "=r"(u) : "f"(x));
    return u;
}
__device__ __forceinline__ float tfbits(float x) { return __uint_as_float(f2tf(x)); }

__device__ __forceinline__ void mma_tf32(float* c, const unsigned* a, const unsigned* b) {
    asm volatile(
        "mma.sync.aligned.m16n8k8.row.col.f32.tf32.tf32.f32 "
        "{%0,%1,%2,%3}, {%4,%5,%6,%7}, {%8,%9}, {%0,%1,%2,%3};\n"
        : "+f"(c[0]), "+f"(c[1]), "+f"(c[2]), "+f"(c[3])
        : "r"(a[0]), "r"(a[1]), "r"(a[2]), "r"(a[3]),
          "r"(b[0]), "r"(b[1]));
}

// ---------------- RoPE cos/sin table ----------------
__global__ void rope_tab_kernel() {
    int i = blockIdx.x * 256 + threadIdx.x;     // 0..65535
    int p = i & 31, posv = i >> 5;
    float freq = exp2f(-(float)p * (13.287712379549449f / 32.0f));
    float ang = (float)posv * freq;
    float sn, cs;
    sincosf(ang, &sn, &cs);
    g_rope[i] = make_float2(cs, sn);
}

// ============================================================
// tf32 GEMM: C[m,e] = sum_k A[m,k] * W[e,k]  (both K-major, K=1024)
// Block 128x128, BK=16, 8 warps (2m x 4n), warp tile 64x32.
// ROPE=true: fused RoPE epilogue scattering to g_Q/g_K/g_V.
// ROPE=false: reads from g_attn if A==nullptr, plain store to Cout (N=1024).
// ============================================================
#define LDA 20   // smem row stride (floats), padded

template<bool ROPE>
__global__ __launch_bounds__(256)
void gemm_tf32(const float* __restrict__ Ain, const float* __restrict__ W,
               const int* __restrict__ pos, float* __restrict__ Cout)
{
    __shared__ float As[2][128*LDA];
    __shared__ float Bs[2][128*LDA];

    const float* A = ROPE ? Ain : (const float*)g_attn;

    const int tid = threadIdx.x, lane = tid & 31, wrp = tid >> 5;
    const int wm = wrp >> 2, wn = wrp & 3;
    const int g  = lane >> 2, tg = lane & 3;
    const int m0 = blockIdx.y * 128, n0 = blockIdx.x * 128;

    float acc[4][4][4];
    #pragma unroll
    for (int i = 0; i < 4; i++)
        #pragma unroll
        for (int j = 0; j < 4; j++)
            #pragma unroll
            for (int k = 0; k < 4; k++) acc[i][j][k] = 0.f;

    const int lrow = tid >> 2;      // 0..63
    const int lq   = tid & 3;       // float4 index within 16-col strip

    // ---- initial tile (k0 = 0) ----
    {
        #pragma unroll
        for (int h = 0; h < 2; h++) {
            int row = lrow + h*64;
            float4 va = *(const float4*)(A + (size_t)(m0+row)*1024 + lq*4);
            float4 vb = *(const float4*)(W + (size_t)(n0+row)*1024 + lq*4);
            int o = row*LDA + lq*4;
            As[0][o+0]=tfbits(va.x); As[0][o+1]=tfbits(va.y);
            As[0][o+2]=tfbits(va.z); As[0][o+3]=tfbits(va.w);
            Bs[0][o+0]=tfbits(vb.x); Bs[0][o+1]=tfbits(vb.y);
            Bs[0][o+2]=tfbits(vb.z); Bs[0][o+3]=tfbits(vb.w);
        }
    }
    __syncthreads();

    for (int kt = 0; kt < 64; kt++) {
        const int cur = kt & 1;
        float4 pa0, pa1, pb0, pb1;
        if (kt < 63) {
            int k0 = (kt+1)*16;
            pa0 = *(const float4*)(A + (size_t)(m0+lrow   )*1024 + k0 + lq*4);
            pa1 = *(const float4*)(A + (size_t)(m0+lrow+64)*1024 + k0 + lq*4);
            pb0 = *(const float4*)(W + (size_t)(n0+lrow   )*1024 + k0 + lq*4);
            pb1 = *(const float4*)(W + (size_t)(n0+lrow+64)*1024 + k0 + lq*4);
        }

        const float* as = As[cur];
        const float* bs = Bs[cur];
        #pragma unroll
        for (int ks = 0; ks < 2; ks++) {
            unsigned af[4][4], bf[4][2];
            #pragma unroll
            for (int mt = 0; mt < 4; mt++) {
                int base = (wm*64 + mt*16 + g)*LDA + ks*8 + tg;
                af[mt][0] = __float_as_uint(as[base]);
                af[mt][1] = __float_as_uint(as[base + 8*LDA]);
                af[mt][2] = __float_as_uint(as[base + 4]);
                af[mt][3] = __float_as_uint(as[base + 8*LDA + 4]);
            }
            #pragma unroll
            for (int nt = 0; nt < 4; nt++) {
                int base = (wn*32 + nt*8 + g)*LDA + ks*8 + tg;
                bf[nt][0] = __float_as_uint(bs[base]);
                bf[nt][1] = __float_as_uint(bs[base + 4]);
            }
            #pragma unroll
            for (int mt = 0; mt < 4; mt++)
                #pragma unroll
                for (int nt = 0; nt < 4; nt++)
                    mma_tf32(acc[mt][nt], af[mt], bf[nt]);
        }

        if (kt < 63) {
            float* ad = As[cur^1];
            float* bd = Bs[cur^1];
            int o0 = lrow*LDA + lq*4, o1 = (lrow+64)*LDA + lq*4;
            ad[o0+0]=tfbits(pa0.x); ad[o0+1]=tfbits(pa0.y); ad[o0+2]=tfbits(pa0.z); ad[o0+3]=tfbits(pa0.w);
            ad[o1+0]=tfbits(pa1.x); ad[o1+1]=tfbits(pa1.y); ad[o1+2]=tfbits(pa1.z); ad[o1+3]=tfbits(pa1.w);
            bd[o0+0]=tfbits(pb0.x); bd[o0+1]=tfbits(pb0.y); bd[o0+2]=tfbits(pb0.z); bd[o0+3]=tfbits(pb0.w);
            bd[o1+0]=tfbits(pb1.x); bd[o1+1]=tfbits(pb1.y); bd[o1+2]=tfbits(pb1.z); bd[o1+3]=tfbits(pb1.w);
        }
        __syncthreads();
    }

    // ---- epilogue ----
    if (ROPE) {
        const int baseN = n0 + wn*32;
        const int which = baseN >> 10;              // 0:Q 1:K 2:V (constant per block)
        const int h     = (baseN & 1023) >> 6;      // constant per warp
        #pragma unroll
        for (int mt = 0; mt < 4; mt++) {
            int r0 = m0 + wm*64 + mt*16 + g;
            int r1 = r0 + 8;
            int b0i = r0 >> 11, s0 = r0 & 2047;
            int b1i = r1 >> 11, s1 = r1 & 2047;
            if (which == 2) {
                float* d0 = g_V + ((size_t)((b0i*H_ + h)*S_ + s0))*DK_;
                float* d1 = g_V + ((size_t)((b1i*H_ + h)*S_ + s1))*DK_;
                #pragma unroll
                for (int nt = 0; nt < 4; nt++) {
                    int dd = (baseN + nt*8 + 2*tg) & 63;
                    *(float2*)(d0 + dd) = make_float2(acc[mt][nt][0], acc[mt][nt][1]);
                    *(float2*)(d1 + dd) = make_float2(acc[mt][nt][2], acc[mt][nt][3]);
                }
            } else {
                float* gq = (which == 0) ? g_Q : g_K;
                int p0 = pos[r0], p1 = pos[r1];
                float* d0 = gq + ((size_t)((b0i*H_ + h)*S_ + s0))*DK_;
                float* d1 = gq + ((size_t)((b1i*H_ + h)*S_ + s1))*DK_;
                #pragma unroll
                for (int nt = 0; nt < 4; nt++) {
                    int dd = (baseN + nt*8 + 2*tg) & 63;
                    int p  = dd >> 1;
                    float2 cs0 = g_rope[p0*32 + p];
                    float2 cs1 = g_rope[p1*32 + p];
                    float e0 = acc[mt][nt][0], o0 = acc[mt][nt][1];
                    float e1 = acc[mt][nt][2], o1 = acc[mt][nt][3];
                    *(float2*)(d0 + dd) = make_float2(cs0.x*e0 - cs0.y*o0, cs0.y*e0 + cs0.x*o0);
                    *(float2*)(d1 + dd) = make_float2(cs1.x*e1 - cs1.y*o1, cs1.y*e1 + cs1.x*o1);
                }
            }
        }
    } else {
        #pragma unroll
        for (int mt = 0; mt < 4; mt++) {
            int r0 = m0 + wm*64 + mt*16 + g;
            #pragma unroll
            for (int nt = 0; nt < 4; nt++) {
                int col = n0 + wn*32 + nt*8 + 2*tg;
                *(float2*)(Cout + (size_t)r0*1024 + col)     = make_float2(acc[mt][nt][0], acc[mt][nt][1]);
                *(float2*)(Cout + (size_t)(r0+8)*1024 + col) = make_float2(acc[mt][nt][2], acc[mt][nt][3]);
            }
        }
    }
}

// ============================================================
// Flash attention with tf32 mma. Block: 128 q-rows, 8 warps
// (warp owns 16 rows). Key tiles of 64. Softmax all-register.
// ============================================================
#define ABM 128
#define ABN 64
#define KSTR 72   // Ks/Vs smem row stride

__global__ __launch_bounds__(256)
void attn_mma_kernel()
{
    __shared__ float sm[2*ABN*KSTR];   // 9216 floats = 36KB. K at 0, V at 4608.
    float* Ksm = sm;
    float* Vsm = sm + ABN*KSTR;

    const int tid = threadIdx.x, lane = tid & 31, w = tid >> 5;
    const int g = lane >> 2, tg = lane & 3;
    const int bh = blockIdx.y;
    const int m0 = blockIdx.x * ABM;

    const float* Qp = g_Q + (size_t)bh * S_ * DK_;
    const float* Kp = g_K + (size_t)bh * S_ * DK_;
    const float* Vp = g_V + (size_t)bh * S_ * DK_;

    // ---- stage Q into smem (stride 68), extract A-fragments ----
    for (int f = tid; f < ABM*16; f += 256) {
        int row = f >> 4, q = f & 15;
        float4 v = *(const float4*)(Qp + (size_t)(m0+row)*DK_ + q*4);
        int o = row*68 + q*4;
        sm[o+0]=tfbits(v.x); sm[o+1]=tfbits(v.y); sm[o+2]=tfbits(v.z); sm[o+3]=tfbits(v.w);
    }
    __syncthreads();

    unsigned qa[8][4];
    {
        int qr = w*16 + g;
        #pragma unroll
        for (int ks = 0; ks < 8; ks++) {
            int base = qr*68 + ks*8 + tg;
            qa[ks][0] = __float_as_uint(sm[base]);
            qa[ks][1] = __float_as_uint(sm[base + 8*68]);
            qa[ks][2] = __float_as_uint(sm[base + 4]);
            qa[ks][3] = __float_as_uint(sm[base + 8*68 + 4]);
        }
    }
    __syncthreads();

    float o[8][4];
    #pragma unroll
    for (int nt = 0; nt < 8; nt++)
        #pragma unroll
        for (int i = 0; i < 4; i++) o[nt][i] = 0.f;

    float mrow0 = -1e30f, mrow1 = -1e30f, l0 = 0.f, l1 = 0.f;
    const int row0 = m0 + w*16 + g;
    const int row1 = row0 + 8;
    const int fullT = m0 / ABN;            // tiles < fullT need no mask
    const int nT = fullT + 2;

    const int src0 = (lane & ~3) | (tg >> 1);
    const int src2 = src0 | 2;
    const bool oddl = tg & 1;

    for (int t = 0; t < nT; t++) {
        const int n0 = t * ABN;

        // load K,V tiles (tf32-converted)
        for (int f = tid; f < ABN*16; f += 256) {
            int j = f >> 4, q = f & 15;
            float4 kv = *(const float4*)(Kp + (size_t)(n0+j)*DK_ + q*4);
            float4 vv = *(const float4*)(Vp + (size_t)(n0+j)*DK_ + q*4);
            int off = j*KSTR + q*4;
            Ksm[off+0]=tfbits(kv.x); Ksm[off+1]=tfbits(kv.y);
            Ksm[off+2]=tfbits(kv.z); Ksm[off+3]=tfbits(kv.w);
            Vsm[off+0]=tfbits(vv.x); Vsm[off+1]=tfbits(vv.y);
            Vsm[off+2]=tfbits(vv.z); Vsm[off+3]=tfbits(vv.w);
        }
        __syncthreads();

        // ---- scores: S = Q @ K^T ----
        float sc[8][4];
        #pragma unroll
        for (int nt = 0; nt < 8; nt++)
            #pragma unroll
            for (int i = 0; i < 4; i++) sc[nt][i] = 0.f;

        #pragma unroll
        for (int ks = 0; ks < 8; ks++) {
            #pragma unroll
            for (int nt = 0; nt < 8; nt++) {
                unsigned bf[2];
                int base = (nt*8 + g)*KSTR + ks*8 + tg;
                bf[0] = __float_as_uint(Ksm[base]);
                bf[1] = __float_as_uint(Ksm[base + 4]);
                mma_tf32(sc[nt], qa[ks], bf);
            }
        }

        // scale + causal mask
        if (t >= fullT) {
            #pragma unroll
            for (int nt = 0; nt < 8; nt++) {
                int c0 = n0 + nt*8 + 2*tg, c1 = c0 + 1;
                sc[nt][0] = (c0 <= row0) ? sc[nt][0]*0.125f : -1e30f;
                sc[nt][1] = (c1 <= row0) ? sc[nt][1]*0.125f : -1e30f;
                sc[nt][2] = (c0 <= row1) ? sc[nt][2]*0.125f : -1e30f;
                sc[nt][3] = (c1 <= row1) ? sc[nt][3]*0.125f : -1e30f;
            }
        } else {
            #pragma unroll
            for (int nt = 0; nt < 8; nt++)
                #pragma unroll
                for (int i = 0; i < 4; i++) sc[nt][i] *= 0.125f;
        }

        // ---- online softmax (all-register, shfl row reductions) ----
        float mx0 = -1e30f, mx1 = -1e30f;
        #pragma unroll
        for (int nt = 0; nt < 8; nt++) {
            mx0 = fmaxf(mx0, fmaxf(sc[nt][0], sc[nt][1]));
            mx1 = fmaxf(mx1, fmaxf(sc[nt][2], sc[nt][3]));
        }
        mx0 = fmaxf(mx0, __shfl_xor_sync(0xffffffffu, mx0, 1));
        mx0 = fmaxf(mx0, __shfl_xor_sync(0xffffffffu, mx0, 2));
        mx1 = fmaxf(mx1, __shfl_xor_sync(0xffffffffu, mx1, 1));
        mx1 = fmaxf(mx1, __shfl_xor_sync(0xffffffffu, mx1, 2));

        float mn0 = fmaxf(mrow0, mx0), mn1 = fmaxf(mrow1, mx1);
        float al0 = __expf(mrow0 - mn0), al1 = __expf(mrow1 - mn1);
        mrow0 = mn0; mrow1 = mn1;

        float ls0 = 0.f, ls1 = 0.f;
        #pragma unroll
        for (int nt = 0; nt < 8; nt++) {
            float p0 = __expf(sc[nt][0] - mn0);
            float p1 = __expf(sc[nt][1] - mn0);
            float p2 = __expf(sc[nt][2] - mn1);
            float p3 = __expf(sc[nt][3] - mn1);
            sc[nt][0]=p0; sc[nt][1]=p1; sc[nt][2]=p2; sc[nt][3]=p3;
            ls0 += p0 + p1; ls1 += p2 + p3;
        }
        ls0 += __shfl_xor_sync(0xffffffffu, ls0, 1);
        ls0 += __shfl_xor_sync(0xffffffffu, ls0, 2);
        ls1 += __shfl_xor_sync(0xffffffffu, ls1, 1);
        ls1 += __shfl_xor_sync(0xffffffffu, ls1, 2);
        l0 = l0*al0 + ls0;
        l1 = l1*al1 + ls1;

        #pragma unroll
        for (int nt = 0; nt < 8; nt++) {
            o[nt][0] *= al0; o[nt][1] *= al0;
            o[nt][2] *= al1; o[nt][3] *= al1;
        }

        // ---- PV: O += P @ V ----
        #pragma unroll
        for (int ks = 0; ks < 8; ks++) {
            // C-frag -> A-frag layout conversion via shuffles
            float v00 = __shfl_sync(0xffffffffu, sc[ks][0], src0);
            float v01 = __shfl_sync(0xffffffffu, sc[ks][1], src0);
            float v10 = __shfl_sync(0xffffffffu, sc[ks][2], src0);
            float v11 = __shfl_sync(0xffffffffu, sc[ks][3], src0);
            float v20 = __shfl_sync(0xffffffffu, sc[ks][0], src2);
            float v21 = __shfl_sync(0xffffffffu, sc[ks][1], src2);
            float v30 = __shfl_sync(0xffffffffu, sc[ks][2], src2);
            float v31 = __shfl_sync(0xffffffffu, sc[ks][3], src2);
            unsigned pa[4];
            pa[0] = f2tf(oddl ? v01 : v00);
            pa[1] = f2tf(oddl ? v11 : v10);
            pa[2] = f2tf(oddl ? v21 : v20);
            pa[3] = f2tf(oddl ? v31 : v30);
            #pragma unroll
            for (int nt = 0; nt < 8; nt++) {
                unsigned bf[2];
                int base = (ks*8 + tg)*KSTR + nt*8 + g;
                bf[0] = __float_as_uint(Vsm[base]);
                bf[1] = __float_as_uint(Vsm[base + 4*KSTR]);
                mma_tf32(o[nt], pa, bf);
            }
        }
        __syncthreads();
    }

    // ---- epilogue: normalize + write to g_attn ([b*S+s][h*64+d]) ----
    const float il0 = 1.0f / l0, il1 = 1.0f / l1;
    const int bb = bh >> 4, hh = bh & 15;
    float* dst0 = g_attn + ((size_t)(bb*S_ + row0))*D_ + hh*DK_;
    float* dst1 = g_attn + ((size_t)(bb*S_ + row1))*D_ + hh*DK_;
    #pragma unroll
    for (int nt = 0; nt < 8; nt++) {
        int d = nt*8 + 2*tg;
        *(float2*)(dst0 + d) = make_float2(o[nt][0]*il0, o[nt][1]*il0);
        *(float2*)(dst1 + d) = make_float2(o[nt][2]*il1, o[nt][3]*il1);
    }
}

// ============================================================
// Launch
// ============================================================
extern "C" void kernel_launch(void* const* d_in, const int* in_sizes, int n_in,
                              void* d_out, int out_size)
{
    const float* x    = (const float*)d_in[0];
    const int*   pos  = (const int*)  d_in[1];
    const float* wqkv = (const float*)d_in[2];
    const float* wo   = (const float*)d_in[3];
    float* out = (float*)d_out;

    (void)in_sizes; (void)n_in; (void)out_size;

    rope_tab_kernel<<<256, 256>>>();
    gemm_tf32<true ><<<dim3(NQKV/128, M_/128), 256>>>(x, wqkv, pos, nullptr);
    attn_mma_kernel<<<dim3(S_/ABM, B_*H_), 256>>>();
    gemm_tf32<false><<<dim3(D_/128, M_/128), 256>>>(nullptr, wo, pos, out);
}